// round 1
// baseline (speedup 1.0000x reference)
#include <cuda_runtime.h>
#include <math.h>

#define BB   1024
#define TT   512
#define HH   64
#define G4   256      // 4*H
#define KK   128      // D + H (both 64)
#define ROWS 8        // batch rows per CTA
#define NTHR 256

// Scratch (static __device__ arrays are the allowed scratch mechanism)
__device__ float g_h1[(size_t)BB * TT * HH];   // layer-0 hidden sequence, [B][T][H]
__device__ float g_hlast[BB * HH];             // layer-1 final hidden state

__device__ __forceinline__ float fsigmoid(float x) {
    return 1.0f / (1.0f + __expf(-x));
}
__device__ __forceinline__ float ftanh(float x) {
    // tanh(|x|) = (1 - e^{-2|x|}) / (1 + e^{-2|x|}), then restore sign (overflow-safe)
    float ax = fabsf(x);
    float e  = __expf(-2.0f * ax);
    float t  = (1.0f - e) / (1.0f + e);
    return copysignf(t, x);
}

// One LSTM layer, batch-first, PyTorch gate order (i,f,g,o).
// Each CTA: 8 batch rows. Threads: 4 groups x 64 lanes; group handles 2 rows.
// Lane j computes gates (i,f,g,o) of hidden unit j for its 2 rows, so it can
// update c_j and h_j locally each step (no cross-lane reduction).
// Combined input vector v = [h(64) ; x(64)], combined transposed weights
// wT[k][j*4+q] in SMEM (float4 per lane per k, conflict-free).
__global__ void __launch_bounds__(NTHR, 1)
lstm_layer(const float* __restrict__ x_in,
           const float* __restrict__ w_ih, const float* __restrict__ w_hh,
           const float* __restrict__ b_ih, const float* __restrict__ b_hh,
           int store_seq, int store_last, int x_is_scratch)
{
    extern __shared__ float sm[];
    float* wT    = sm;               // [128][256] = 32768 floats (128 KB)
    float* inbuf = sm + KK * G4;     // [2][8][128] = 2048 floats (8 KB)

    const float* xp = x_is_scratch ? g_h1 : x_in;

    const int tid = threadIdx.x;
    const int j   = tid & 63;        // hidden unit
    const int grp = tid >> 6;        // 0..3
    const int lr0 = grp * 2;
    const int lr1 = grp * 2 + 1;
    const int row_base = blockIdx.x * ROWS;

    // ---- stage combined transposed weights: wT[k*256 + jj*4 + q] ----
    // v[k] = h[k] for k<64, x[k-64] for k>=64
    for (int idx = tid; idx < KK * G4; idx += NTHR) {
        int k  = idx >> 8;
        int c  = idx & 255;
        int jj = c >> 2;
        int q  = c & 3;
        int g  = q * 64 + jj;
        float w = (k < 64) ? w_hh[g * 64 + k] : w_ih[g * 64 + (k - 64)];
        wT[idx] = w;
    }

    // ---- init double buffer 0: h part = 0, x part = x[:, t=0, :] ----
    {
        int r = tid >> 6, d = tid & 63;
        inbuf[(0 * 8 + r    ) * KK + d] = 0.0f;
        inbuf[(0 * 8 + r + 4) * KK + d] = 0.0f;
        inbuf[(0 * 8 + r    ) * KK + 64 + d] = xp[((size_t)(row_base + r    )) * TT * HH + d];
        inbuf[(0 * 8 + r + 4) * KK + 64 + d] = xp[((size_t)(row_base + r + 4)) * TT * HH + d];
    }

    // per-lane combined bias (b_ih + b_hh), gate q of unit j
    float bq0 = b_ih[0 * 64 + j] + b_hh[0 * 64 + j];
    float bq1 = b_ih[1 * 64 + j] + b_hh[1 * 64 + j];
    float bq2 = b_ih[2 * 64 + j] + b_hh[2 * 64 + j];
    float bq3 = b_ih[3 * 64 + j] + b_hh[3 * 64 + j];

    float cc0 = 0.0f, cc1 = 0.0f;    // cell state for the 2 rows

    // x prefetch mapping (all 256 threads, 2 elements each: rows r and r+4)
    const int xr = tid >> 6, xd = tid & 63;
    const float* xrow0 = xp + ((size_t)(row_base + xr    )) * TT * HH + xd;
    const float* xrow1 = xp + ((size_t)(row_base + xr + 4)) * TT * HH + xd;

    __syncthreads();

    int p = 0;
    for (int t = 0; t < TT; t++) {
        // prefetch next step's x (global latency hidden under the k-loop)
        int tn = (t + 1 < TT) ? (t + 1) : t;
        float xa = xrow0[(size_t)tn * HH];
        float xb = xrow1[(size_t)tn * HH];

        float a00 = bq0, a10 = bq1, a20 = bq2, a30 = bq3;  // row lr0
        float a01 = bq0, a11 = bq1, a21 = bq2, a31 = bq3;  // row lr1

        const float*  in0 = &inbuf[(p * 8 + lr0) * KK];
        const float*  in1 = &inbuf[(p * 8 + lr1) * KK];
        const float4* wp  = (const float4*)wT + j;   // row k -> +64 float4

        #pragma unroll 16
        for (int k = 0; k < KK; k++) {
            float  v0 = in0[k];
            float  v1 = in1[k];
            float4 w  = wp[(size_t)k * 64];
            a00 += v0 * w.x; a10 += v0 * w.y; a20 += v0 * w.z; a30 += v0 * w.w;
            a01 += v1 * w.x; a11 += v1 * w.y; a21 += v1 * w.z; a31 += v1 * w.w;
        }

        // gate activations + state update (PyTorch order: i, f, g, o)
        float i0 = fsigmoid(a00), f0 = fsigmoid(a10), g0 = ftanh(a20), o0 = fsigmoid(a30);
        cc0 = f0 * cc0 + i0 * g0;
        float h0 = o0 * ftanh(cc0);

        float i1 = fsigmoid(a01), f1 = fsigmoid(a11), g1 = ftanh(a21), o1 = fsigmoid(a31);
        cc1 = f1 * cc1 + i1 * g1;
        float h1v = o1 * ftanh(cc1);

        int np = p ^ 1;
        // write new h into the other buffer
        inbuf[(np * 8 + lr0) * KK + j] = h0;
        inbuf[(np * 8 + lr1) * KK + j] = h1v;
        // write prefetched x into the other buffer
        inbuf[(np * 8 + xr    ) * KK + 64 + xd] = xa;
        inbuf[(np * 8 + xr + 4) * KK + 64 + xd] = xb;

        if (store_seq) {
            g_h1[((size_t)(row_base + lr0) * TT + t) * HH + j] = h0;
            g_h1[((size_t)(row_base + lr1) * TT + t) * HH + j] = h1v;
        }
        if (store_last && t == TT - 1) {
            g_hlast[(row_base + lr0) * HH + j] = h0;
            g_hlast[(row_base + lr1) * HH + j] = h1v;
        }

        __syncthreads();
        p = np;
    }
}

// out[b][o] = softplus(h_last[b] . fc_w[o] + fc_b[o]),  O=32
__global__ void fc_softplus(const float* __restrict__ fc_w,
                            const float* __restrict__ fc_b,
                            float* __restrict__ out)
{
    __shared__ float wsh[64 * 32];   // [k][o] transposed, conflict-free
    __shared__ float bsh[32];
    const int tid = threadIdx.x;     // 128 threads

    for (int idx = tid; idx < 64 * 32; idx += 128) {
        int k = idx >> 5, o = idx & 31;
        wsh[idx] = fc_w[o * 64 + k];
    }
    if (tid < 32) bsh[tid] = fc_b[tid];
    __syncthreads();

    int gid = blockIdx.x * 128 + tid;
    int b = gid >> 5, o = gid & 31;
    const float* hr = g_hlast + b * 64;

    float z = bsh[o];
    #pragma unroll
    for (int k = 0; k < 64; k++)
        z += hr[k] * wsh[k * 32 + o];

    float r = (z > 20.0f) ? z : log1pf(__expf(z));
    out[gid] = r;
}

extern "C" void kernel_launch(void* const* d_in, const int* in_sizes, int n_in,
                              void* d_out, int out_size)
{
    (void)in_sizes; (void)n_in; (void)out_size;
    const float* x    = (const float*)d_in[0];
    const float* wih0 = (const float*)d_in[1];
    const float* whh0 = (const float*)d_in[2];
    const float* bih0 = (const float*)d_in[3];
    const float* bhh0 = (const float*)d_in[4];
    const float* wih1 = (const float*)d_in[5];
    const float* whh1 = (const float*)d_in[6];
    const float* bih1 = (const float*)d_in[7];
    const float* bhh1 = (const float*)d_in[8];
    const float* fcw  = (const float*)d_in[9];
    const float* fcb  = (const float*)d_in[10];
    float* out = (float*)d_out;

    const size_t smem = (size_t)(KK * G4 + 2 * 8 * KK) * sizeof(float);  // 139264 B
    cudaFuncSetAttribute(lstm_layer, cudaFuncAttributeMaxDynamicSharedMemorySize, (int)smem);

    // layer 0: reads x input, stores full h1 sequence to scratch
    lstm_layer<<<BB / ROWS, NTHR, smem>>>(x, wih0, whh0, bih0, bhh0,
                                          /*store_seq=*/1, /*store_last=*/0, /*x_is_scratch=*/0);
    // layer 1: reads h1 scratch, stores only final h to g_hlast
    lstm_layer<<<BB / ROWS, NTHR, smem>>>(nullptr, wih1, whh1, bih1, bhh1,
                                          /*store_seq=*/0, /*store_last=*/1, /*x_is_scratch=*/1);
    // FC + softplus
    fc_softplus<<<(BB * 32) / 128, 128>>>(fcw, fcb, out);
}

// round 2
// speedup vs baseline: 1.1683x; 1.1683x over previous
#include <cuda_runtime.h>
#include <math.h>

#define BB   1024
#define TT   512
#define HH   64
#define KK   128
#define ROWS 8
#define NTHR 256
#define VPITCH 132          // words per input row in smem (conflict-free padding)
#define LOG2E 1.4426950408889634f

// Scratch (static __device__ arrays are the allowed scratch mechanism)
__device__ float g_h1[(size_t)BB * TT * HH];   // layer-0 hidden sequence [B][T][H]
__device__ float g_hlast[BB * HH];             // layer-1 final hidden state

__device__ __forceinline__ void fma2(unsigned long long &d,
                                     unsigned long long a, unsigned long long b) {
    asm("fma.rn.f32x2 %0, %1, %2, %0;" : "+l"(d) : "l"(a), "l"(b));
}
__device__ __forceinline__ float ex2f(float x) {
    float r; asm("ex2.approx.f32 %0, %1;" : "=f"(r) : "f"(x)); return r;
}
__device__ __forceinline__ float rcpf(float x) {
    float r; asm("rcp.approx.f32 %0, %1;" : "=f"(r) : "f"(x)); return r;
}
__device__ __forceinline__ float2 unpack2(unsigned long long v) {
    float2 f; asm("mov.b64 {%0, %1}, %2;" : "=f"(f.x), "=f"(f.y) : "l"(v)); return f;
}

// One LSTM layer, batch-first, PyTorch gate order (i,f,g,o).
// CTA = 8 batch rows, 256 threads. Thread (j = tid>>2, q = tid&3) computes
// gate q of unit j for all 8 rows; accumulators are fp32x2 packed over k-parity
// so FFMA2 operands come straight from LDS.128 (no packing in the loop).
// Weights are read once per CTA per step (no duplication across row groups).
// Gate exchange for the c/h update is intra-quad via shuffles: lane (jj,s)
// ends up owning rows {2s, 2s+1} of unit j with all four gates.
__global__ void __launch_bounds__(NTHR, 1)
lstm_layer(const float* __restrict__ x_in,
           const float* __restrict__ w_ih, const float* __restrict__ w_hh,
           const float* __restrict__ b_ih, const float* __restrict__ b_hh,
           int store_seq, int store_last, int x_is_scratch)
{
    extern __shared__ float sm[];
    float* wq = sm;                    // [32 kk][256 col][4 kp] = 32768 floats (128 KB)
    float* ib = sm + KK * 256;         // [2 buf][8 rows][VPITCH] = 2112 floats

    const float* xp = x_is_scratch ? g_h1 : x_in;

    const int tid  = threadIdx.x;
    const int lane = tid & 31;
    const int j    = tid >> 2;         // unit 0..63
    const int q    = tid & 3;          // gate (i,f,g,o)
    const int s    = lane & 3;         // row-pair this lane owns after exchange
    const int qbase = lane & ~3;       // quad base lane
    const int row_base = blockIdx.x * ROWS;

    // ---- stage weights: wq[kk*1024 + col*4 + kp], col = j*4 + q, k = kk*4 + kp
    for (int idx = tid; idx < KK * 256; idx += NTHR) {
        int kp = idx & 3;
        int c  = (idx >> 2) & 255;
        int kk = idx >> 10;
        int k  = kk * 4 + kp;
        int ju = c >> 2, qu = c & 3;
        int g  = qu * 64 + ju;
        wq[idx] = (k < 64) ? w_hh[g * 64 + k] : w_ih[g * 64 + (k - 64)];
    }

    // ---- init buffer 0: h part = 0, x part = x[:, 0, :]
    {
        int r = tid & 7, u = tid >> 3;   // u 0..31
        ib[r * VPITCH + u]      = 0.0f;
        ib[r * VPITCH + u + 32] = 0.0f;
        ib[r * VPITCH + 64 + u] = xp[(size_t)(row_base + r) * TT * HH + u];
        ib[r * VPITCH + 96 + u] = xp[(size_t)(row_base + r) * TT * HH + 32 + u];
    }

    const float bias = b_ih[q * 64 + j] + b_hh[q * 64 + j];
    // branch-free activation: sigmoid for q!=2, tanh(z)=2*sigmoid(2z)-1 for q==2
    const float mscale = (q == 2) ? (-2.0f * LOG2E) : (-LOG2E);
    const float po     = (q == 2) ? 2.0f : 1.0f;
    const float pc     = (q == 2) ? -1.0f : 0.0f;

    float c0 = 0.0f, c1 = 0.0f;        // cell state, rows 2s / 2s+1 of unit j

    // x prefetch mapping: thread covers (row xr, dims xd and xd+32)
    const int xr = tid & 7, xd = tid >> 3;
    const float* xrow = xp + (size_t)(row_base + xr) * TT * HH + xd;

    __syncthreads();

    int pb = 0;
    for (int t = 0; t < TT; t++) {
        int tn = (t + 1 < TT) ? (t + 1) : t;
        float xa = xrow[(size_t)tn * HH];
        float xb = xrow[(size_t)tn * HH + 32];

        unsigned long long acc[8];
        #pragma unroll
        for (int r = 0; r < 8; r++) acc[r] = 0ull;

        const float* vb = ib + pb * (8 * VPITCH);
        const float* wp = wq + tid * 4;

        #pragma unroll 8
        for (int kk = 0; kk < 32; kk++) {
            ulonglong2 w2 = *reinterpret_cast<const ulonglong2*>(wp + (size_t)kk * 1024);
            #pragma unroll
            for (int r = 0; r < 8; r++) {
                ulonglong2 v2 = *reinterpret_cast<const ulonglong2*>(vb + r * VPITCH + kk * 4);
                fma2(acc[r], v2.x, w2.x);   // {k,k+1} halves
                fma2(acc[r], v2.y, w2.y);   // {k+2,k+3} halves
            }
        }

        // ---- reduce halves + bias + activation (my gate, all 8 rows)
        float act[8];
        #pragma unroll
        for (int r = 0; r < 8; r++) {
            float2 fr = unpack2(acc[r]);
            float z = (fr.x + fr.y) + bias;
            float e = ex2f(z * mscale);
            act[r] = fmaf(rcpf(1.0f + e), po, pc);
        }

        // ---- intra-quad exchange: lane (jj,s) gathers i,f,g,o for rows {2s,2s+1}
        unsigned plo[4], phi[4];
        #pragma unroll
        for (int p = 0; p < 4; p++) {
            plo[p] = __float_as_uint(act[2 * p]);
            phi[p] = __float_as_uint(act[2 * p + 1]);
        }
        unsigned glo[4] = {0, 0, 0, 0}, ghi[4] = {0, 0, 0, 0};
        #pragma unroll
        for (int p = 0; p < 4; p++) {
            #pragma unroll
            for (int qq = 0; qq < 4; qq++) {
                unsigned a  = __shfl_sync(0xffffffffu, plo[p], qbase + qq);
                unsigned b2 = __shfl_sync(0xffffffffu, phi[p], qbase + qq);
                if (s == p) { glo[qq] = a; ghi[qq] = b2; }
            }
        }

        float i0 = __uint_as_float(glo[0]), i1 = __uint_as_float(ghi[0]);
        float f0 = __uint_as_float(glo[1]), f1 = __uint_as_float(ghi[1]);
        float g0 = __uint_as_float(glo[2]), g1 = __uint_as_float(ghi[2]);
        float o0 = __uint_as_float(glo[3]), o1 = __uint_as_float(ghi[3]);

        c0 = f0 * c0 + i0 * g0;
        c1 = f1 * c1 + i1 * g1;
        float th0 = fmaf(rcpf(1.0f + ex2f(c0 * (-2.0f * LOG2E))), 2.0f, -1.0f);
        float th1 = fmaf(rcpf(1.0f + ex2f(c1 * (-2.0f * LOG2E))), 2.0f, -1.0f);
        float h0 = o0 * th0;
        float h1 = o1 * th1;

        // ---- write next-step inputs into the other buffer
        float* nb = ib + (pb ^ 1) * (8 * VPITCH);
        int r0 = s * 2;
        nb[r0 * VPITCH + j]       = h0;
        nb[(r0 + 1) * VPITCH + j] = h1;
        nb[xr * VPITCH + 64 + xd] = xa;
        nb[xr * VPITCH + 96 + xd] = xb;

        if (store_seq) {
            g_h1[((size_t)(row_base + r0) * TT + t) * HH + j]     = h0;
            g_h1[((size_t)(row_base + r0 + 1) * TT + t) * HH + j] = h1;
        }
        if (store_last && t == TT - 1) {
            g_hlast[(row_base + r0) * HH + j]     = h0;
            g_hlast[(row_base + r0 + 1) * HH + j] = h1;
        }

        __syncthreads();
        pb ^= 1;
    }
}

// out[b][o] = softplus(h_last[b] . fc_w[o] + fc_b[o]),  O=32
__global__ void fc_softplus(const float* __restrict__ fc_w,
                            const float* __restrict__ fc_b,
                            float* __restrict__ out)
{
    __shared__ float wsh[64 * 32];   // [k][o] transposed
    __shared__ float bsh[32];
    const int tid = threadIdx.x;     // 128 threads

    for (int idx = tid; idx < 64 * 32; idx += 128) {
        int k = idx >> 5, o = idx & 31;
        wsh[idx] = fc_w[o * 64 + k];
    }
    if (tid < 32) bsh[tid] = fc_b[tid];
    __syncthreads();

    int gid = blockIdx.x * 128 + tid;
    int b = gid >> 5, o = gid & 31;
    const float* hr = g_hlast + b * 64;

    float z = bsh[o];
    #pragma unroll
    for (int k = 0; k < 64; k++)
        z += hr[k] * wsh[k * 32 + o];

    float r = (z > 20.0f) ? z : log1pf(__expf(z));
    out[gid] = r;
}

extern "C" void kernel_launch(void* const* d_in, const int* in_sizes, int n_in,
                              void* d_out, int out_size)
{
    (void)in_sizes; (void)n_in; (void)out_size;
    const float* x    = (const float*)d_in[0];
    const float* wih0 = (const float*)d_in[1];
    const float* whh0 = (const float*)d_in[2];
    const float* bih0 = (const float*)d_in[3];
    const float* bhh0 = (const float*)d_in[4];
    const float* wih1 = (const float*)d_in[5];
    const float* whh1 = (const float*)d_in[6];
    const float* bih1 = (const float*)d_in[7];
    const float* bhh1 = (const float*)d_in[8];
    const float* fcw  = (const float*)d_in[9];
    const float* fcb  = (const float*)d_in[10];
    float* out = (float*)d_out;

    const size_t smem = (size_t)(KK * 256 + 2 * 8 * VPITCH) * sizeof(float); // 139,520 B
    cudaFuncSetAttribute(lstm_layer, cudaFuncAttributeMaxDynamicSharedMemorySize, (int)smem);

    // layer 0: reads x, stores full h1 sequence
    lstm_layer<<<BB / ROWS, NTHR, smem>>>(x, wih0, whh0, bih0, bhh0, 1, 0, 0);
    // layer 1: reads h1 scratch, stores only final h
    lstm_layer<<<BB / ROWS, NTHR, smem>>>(nullptr, wih1, whh1, bih1, bhh1, 0, 1, 1);
    // FC + softplus
    fc_softplus<<<(BB * 32) / 128, 128>>>(fcw, fcb, out);
}